// round 2
// baseline (speedup 1.0000x reference)
#include <cuda_runtime.h>

#define Nn 65536
#define Kk 16
#define NK (Nn*Kk)

typedef unsigned long long ull;

__device__ __forceinline__ ull pk2(float lo, float hi){
    ull r; asm("mov.b64 %0, {%1,%2};" : "=l"(r) : "f"(lo), "f"(hi)); return r;
}
__device__ __forceinline__ float2 upk2(ull v){
    float2 r; asm("mov.b64 {%0,%1}, %2;" : "=f"(r.x), "=f"(r.y) : "l"(v)); return r;
}
__device__ __forceinline__ void ffma2(ull &acc, ull a, ull b){
    asm("fma.rn.f32x2 %0, %1, %2, %0;" : "+l"(acc) : "l"(a), "l"(b));
}

// ---------------- scratch (device globals; no allocation) ----------------
__device__ float g_M1[10];      // sum of concat features
__device__ float g_M2[55];      // upper-triangle second moments
__device__ float g_w1p[1280];   // folded w1' = w1 * a1   (10 x 128)
__device__ float g_c1[128];     // folded const = be1 - m*a1
__device__ float g_sum2[64];
__device__ float g_sumsq2[64];
__device__ float g_a2[64];
__device__ float g_c2[64];

// ---------------- K0: zero accumulators (graph-replay safe) --------------
__global__ void k_zero(){
    int t = threadIdx.x;
    if (t < 10) g_M1[t] = 0.f;
    if (t < 55) g_M2[t] = 0.f;
    if (t < 64){ g_sum2[t] = 0.f; g_sumsq2[t] = 0.f; }
}

// ---------------- K1: moments of concat over all (n,k) -------------------
__global__ void k_stats(const float* __restrict__ p){
    float m1[10], m2[55];
#pragma unroll
    for (int i=0;i<10;i++) m1[i]=0.f;
#pragma unroll
    for (int i=0;i<55;i++) m2[i]=0.f;
    int tid = blockIdx.x*blockDim.x + threadIdx.x;
    int nth = gridDim.x*blockDim.x;
    for (int r = tid; r < NK; r += nth){
        int n = r >> 4, k = r & 15;
        const float* pc = p + n*48;
        float c[10];
        c[0]=pc[0];     c[1]=pc[1];     c[2]=pc[2];
        c[3]=pc[3*k];   c[4]=pc[3*k+1]; c[5]=pc[3*k+2];
        c[6]=c[0]-c[3]; c[7]=c[1]-c[4]; c[8]=c[2]-c[5];
        c[9]=sqrtf(c[6]*c[6]+c[7]*c[7]+c[8]*c[8]);
        int t = 0;
#pragma unroll
        for (int a=0;a<10;a++){
            m1[a] += c[a];
#pragma unroll
            for (int b=a;b<10;b++) m2[t++] += c[a]*c[b];
        }
    }
#pragma unroll
    for (int off=16; off>0; off>>=1){
#pragma unroll
        for (int i=0;i<10;i++) m1[i] += __shfl_down_sync(0xffffffffu, m1[i], off);
#pragma unroll
        for (int i=0;i<55;i++) m2[i] += __shfl_down_sync(0xffffffffu, m2[i], off);
    }
    if ((threadIdx.x & 31) == 0){
#pragma unroll
        for (int i=0;i<10;i++) atomicAdd(&g_M1[i], m1[i]);
#pragma unroll
        for (int i=0;i<55;i++) atomicAdd(&g_M2[i], m2[i]);
    }
}

// ---------------- K2: fold BN1 into w1 (exact analytic moments) ----------
__global__ void k_fold(const float* __restrict__ w1, const float* __restrict__ b1,
                       const float* __restrict__ g1, const float* __restrict__ be1){
    int d = threadIdx.x;   // 128 threads
    const double invNK = 1.0 / (double)NK;
    double wv[10];
#pragma unroll
    for (int c=0;c<10;c++) wv[c] = (double)w1[c*128 + d];
    double m = 0.0;
#pragma unroll
    for (int c=0;c<10;c++) m += ((double)g_M1[c]*invNK) * wv[c];
    double q = 0.0;
    int t = 0;
#pragma unroll
    for (int a=0;a<10;a++){
#pragma unroll
        for (int b=a;b<10;b++){
            double s2 = (double)g_M2[t++] * invNK;
            double term = s2 * wv[a] * wv[b];
            q += (a==b) ? term : 2.0*term;
        }
    }
    double var = q - m*m;                    // b1 cancels exactly
    double a1  = (double)g1[d] / sqrt(var + 1e-5);
    g_c1[d] = (float)((double)be1[d] - m*a1);
#pragma unroll
    for (int c=0;c<10;c++) g_w1p[c*128 + d] = (float)(wv[c]*a1);
    (void)b1;
}

// ---------------- K3: fused main kernel ----------------------------------
// smem layout (floats)
#define SM_W1P 0
#define SM_C1  1280
#define SM_B2  1408
#define SM_BO  1472
#define SM_W2  1536
#define SM_WS  9728
#define SM_WO  26112
#define SM_BASE 34304
#define SUBSZ 4672
// per sub-block: h[0..2047] px[2048..4095] cc[4096..4287] fx[4288..4415]
//                ob[4416..4543] s2[4544..4607] ss2[4608..4671]
#define SMEM_FLOATS (SM_BASE + 4*SUBSZ)   // 52992 floats = 211968 B

__global__ void __launch_bounds__(512,1) k_main(
    const float* __restrict__ p, const float* __restrict__ x,
    const float* __restrict__ w2, const float* __restrict__ b2,
    const float* __restrict__ ws, const float* __restrict__ wo,
    const float* __restrict__ bo, float* __restrict__ out)
{
    extern __shared__ float sm[];
    int tid = threadIdx.x;
    int s = tid >> 7;        // sub-block 0..3 (one point each)
    int u = tid & 127;
    float* hS  = sm + SM_BASE + s*SUBSZ;
    float* pxS = hS + 2048;
    float* ccS = hS + 4096;
    float* fxS = hS + 4288;
    float* obS = hS + 4416;
    float* s2S = hS + 4544;
    float* ss2S= hS + 4608;

    for (int i = tid; i < 1280;  i += 512) sm[SM_W1P+i] = g_w1p[i];
    for (int i = tid; i < 128;   i += 512) sm[SM_C1+i]  = g_c1[i];
    if (tid < 64){ sm[SM_B2+tid] = b2[tid]; sm[SM_BO+tid] = bo[tid]; }
    for (int i = tid; i < 8192;  i += 512) sm[SM_W2+i] = w2[i];
    for (int i = tid; i < 16384; i += 512) sm[SM_WS+i] = ws[i];
    for (int i = tid; i < 8192;  i += 512) sm[SM_WO+i] = wo[i];
    if (u < 64){ s2S[u]=0.f; ss2S[u]=0.f; }
    __syncthreads();

    const float* w2s = sm + SM_W2;
    const float* wss = sm + SM_WS;
    const float* wos = sm + SM_WO;

    for (int g = blockIdx.x; g < Nn/4; g += gridDim.x){
        int n = g*4 + s;

        // stage x into px[:,64:128]
        const float4* xv = (const float4*)(x + (size_t)n*1024);
#pragma unroll
        for (int f = 0; f < 2; f++){
            int fi = u + f*128;
            int k = fi >> 4, j4 = fi & 15;
            *(float4*)&pxS[k*128 + 64 + 4*j4] = xv[fi];
        }
        if (u < 48) obS[u] = p[n*48 + u];
        __syncthreads();
        if (u < 16){
            int k = u;
            float cx=obS[0], cy=obS[1], cz=obS[2];
            float qx=obS[3*k], qy=obS[3*k+1], qz=obS[3*k+2];
            float dx=cx-qx, dy=cy-qy, dz=cz-qz;
            float* c = ccS + 12*k;
            c[0]=cx;c[1]=cy;c[2]=cz;c[3]=qx;c[4]=qy;c[5]=qz;
            c[6]=dx;c[7]=dy;c[8]=dz;
            c[9]=sqrtf(dx*dx+dy*dy+dz*dz);
        }
        __syncthreads();

        // h = relu(concat @ w1' + c1)   (BN1 pre-folded)
        {
            float w[10];
#pragma unroll
            for (int c=0;c<10;c++) w[c] = sm[SM_W1P + c*128 + u];
            float cl = sm[SM_C1 + u];
#pragma unroll
            for (int k=0;k<16;k++){
                const float* cr = ccS + 12*k;
                float acc = cl;
#pragma unroll
                for (int c=0;c<10;c++) acc = fmaf(cr[c], w[c], acc);
                hS[k*128 + u] = fmaxf(acc, 0.f);
            }
        }
        __syncthreads();

        // p_c = h @ w2 + b2  -> px[:,0:64]   (f32x2 packed over d-pairs)
        {
            int e = u & 63, kh = u >> 6;
            ull acc[8];
#pragma unroll
            for (int i=0;i<8;i++) acc[i]=0ull;
            const float* hrow = hS + kh*8*128;
            for (int dp=0; dp<64; dp++){
                ull w = pk2(w2s[(2*dp)*64 + e], w2s[(2*dp+1)*64 + e]);
#pragma unroll
                for (int kk=0;kk<8;kk++){
                    ull hp = *(const ull*)(hrow + kk*128 + 2*dp);
                    ffma2(acc[kk], hp, w);
                }
            }
            float bb = sm[SM_B2 + e];
#pragma unroll
            for (int kk=0;kk<8;kk++){
                float2 a = upk2(acc[kk]);
                pxS[(kh*8+kk)*128 + e] = a.x + a.y + bb;
            }
        }
        __syncthreads();

        // logits = px @ ws  -> reuse hS     (f32x2 over c-pairs, 2 e-cols/thread)
        {
            int e0 = u & 63, kh = u >> 6;
            ull acc[16];
#pragma unroll
            for (int i=0;i<16;i++) acc[i]=0ull;
            const float* prow = pxS + kh*8*128;
            for (int cp=0; cp<64; cp++){
                ull w0 = pk2(wss[(2*cp)*128 + e0],      wss[(2*cp+1)*128 + e0]);
                ull w1v= pk2(wss[(2*cp)*128 + e0 + 64], wss[(2*cp+1)*128 + e0 + 64]);
#pragma unroll
                for (int kk=0;kk<8;kk++){
                    ull pp = *(const ull*)(prow + kk*128 + 2*cp);
                    ffma2(acc[kk],   pp, w0);
                    ffma2(acc[8+kk], pp, w1v);
                }
            }
#pragma unroll
            for (int kk=0;kk<8;kk++){
                float2 a = upk2(acc[kk]);
                float2 b = upk2(acc[8+kk]);
                hS[(kh*8+kk)*128 + e0]      = a.x + a.y;
                hS[(kh*8+kk)*128 + e0 + 64] = b.x + b.y;
            }
        }
        __syncthreads();

        // softmax over k (thread-local per channel) + weighted pool
        {
            float l[16];
#pragma unroll
            for (int k=0;k<16;k++) l[k] = hS[k*128 + u];
            float m = l[0];
#pragma unroll
            for (int k=1;k<16;k++) m = fmaxf(m, l[k]);
            float sumv = 0.f;
#pragma unroll
            for (int k=0;k<16;k++){ l[k] = __expf(l[k]-m); sumv += l[k]; }
            float f = 0.f;
#pragma unroll
            for (int k=0;k<16;k++) f = fmaf(l[k], pxS[k*128+u], f);
            fxS[u] = f / sumv;
        }
        __syncthreads();

        // out = feat @ wo + bo  (split-e reduction)
        {
            int j = u & 63, eh = u >> 6;
            float acc = 0.f;
#pragma unroll 8
            for (int e2=0;e2<64;e2++){
                int e = eh*64 + e2;
                acc = fmaf(fxS[e], wos[e*64 + j], acc);
            }
            obS[eh*64 + j] = acc;
        }
        __syncthreads();
        if (u < 64){
            float v = obS[u] + obS[64+u] + sm[SM_BO+u];
            out[(size_t)n*64 + u] = v;
            s2S[u] += v;
            ss2S[u] += v*v;
        }
        __syncthreads();
    }
    if (tid < 64){
        float a=0.f, b=0.f;
#pragma unroll
        for (int si=0; si<4; si++){
            a += sm[SM_BASE + si*SUBSZ + 4544 + tid];
            b += sm[SM_BASE + si*SUBSZ + 4608 + tid];
        }
        atomicAdd(&g_sum2[tid], a);
        atomicAdd(&g_sumsq2[tid], b);
    }
}

// ---------------- K4: finalize BN2 constants ------------------------------
__global__ void k_fin(const float* __restrict__ g2, const float* __restrict__ be2){
    int j = threadIdx.x; // 64
    double inv = 1.0 / (double)Nn;
    double mu  = (double)g_sum2[j] * inv;
    double var = (double)g_sumsq2[j] * inv - mu*mu;
    double a2  = (double)g2[j] / sqrt(var + 1e-5);
    g_a2[j] = (float)a2;
    g_c2[j] = (float)((double)be2[j] - mu*a2);
}

// ---------------- K5: in-place BN2 + relu ---------------------------------
__global__ void k_norm(float* __restrict__ out){
    __shared__ float a2s[64], c2s[64];
    if (threadIdx.x < 64){ a2s[threadIdx.x] = g_a2[threadIdx.x]; c2s[threadIdx.x] = g_c2[threadIdx.x]; }
    __syncthreads();
    const int nq = Nn*64/4;
    float4* o4 = (float4*)out;
    for (int f = blockIdx.x*blockDim.x + threadIdx.x; f < nq; f += gridDim.x*blockDim.x){
        float4 v = o4[f];
        int j = (f*4) & 63;
        v.x = fmaxf(fmaf(v.x, a2s[j],   c2s[j]),   0.f);
        v.y = fmaxf(fmaf(v.y, a2s[j+1], c2s[j+1]), 0.f);
        v.z = fmaxf(fmaf(v.z, a2s[j+2], c2s[j+2]), 0.f);
        v.w = fmaxf(fmaf(v.w, a2s[j+3], c2s[j+3]), 0.f);
        o4[f] = v;
    }
}

// ---------------- launch ---------------------------------------------------
extern "C" void kernel_launch(void* const* d_in, const int* in_sizes, int n_in,
                              void* d_out, int out_size){
    const float* p   = (const float*)d_in[0];
    const float* x   = (const float*)d_in[1];
    const float* w1  = (const float*)d_in[2];
    const float* b1  = (const float*)d_in[3];
    const float* g1  = (const float*)d_in[4];
    const float* be1 = (const float*)d_in[5];
    const float* w2  = (const float*)d_in[6];
    const float* b2  = (const float*)d_in[7];
    const float* ws  = (const float*)d_in[8];
    const float* wo  = (const float*)d_in[9];
    const float* bo  = (const float*)d_in[10];
    const float* g2  = (const float*)d_in[11];
    const float* be2 = (const float*)d_in[12];
    float* out = (float*)d_out;
    (void)in_sizes; (void)n_in; (void)out_size;

    cudaFuncSetAttribute(k_main, cudaFuncAttributeMaxDynamicSharedMemorySize,
                         SMEM_FLOATS*4);

    k_zero<<<1,64>>>();
    k_stats<<<256,256>>>(p);
    k_fold<<<1,128>>>(w1,b1,g1,be1);
    k_main<<<304,512,SMEM_FLOATS*4>>>(p,x,w2,b2,ws,wo,bo,out);
    k_fin<<<1,64>>>(g2,be2);
    k_norm<<<2048,256>>>(out);
}

// round 3
// speedup vs baseline: 1.0014x; 1.0014x over previous
#include <cuda_runtime.h>

#define Nn 65536
#define Kk 16
#define NK (Nn*Kk)

typedef unsigned long long ull;

__device__ __forceinline__ ull pk2(float lo, float hi){
    ull r; asm("mov.b64 %0, {%1,%2};" : "=l"(r) : "f"(lo), "f"(hi)); return r;
}
__device__ __forceinline__ float2 upk2(ull v){
    float2 r; asm("mov.b64 {%0,%1}, %2;" : "=f"(r.x), "=f"(r.y) : "l"(v)); return r;
}
__device__ __forceinline__ void ffma2(ull &acc, ull a, ull b){
    asm("fma.rn.f32x2 %0, %1, %2, %0;" : "+l"(acc) : "l"(a), "l"(b));
}

// ---------------- scratch (device globals; no allocation) ----------------
__device__ float g_M1[10];      // sum of concat features
__device__ float g_M2[55];      // upper-triangle second moments
__device__ float g_w1p[1280];   // folded w1' = w1 * a1   (10 x 128)
__device__ float g_c1[128];     // folded const = be1 - m*a1
__device__ float g_sum2[64];
__device__ float g_sumsq2[64];
__device__ float g_a2[64];
__device__ float g_c2[64];

// ---------------- K0: zero accumulators (graph-replay safe) --------------
__global__ void k_zero(){
    int t = threadIdx.x;
    if (t < 10) g_M1[t] = 0.f;
    if (t < 55) g_M2[t] = 0.f;
    if (t < 64){ g_sum2[t] = 0.f; g_sumsq2[t] = 0.f; }
}

// ---------------- K1: moments of concat over all (n,k) -------------------
__global__ void k_stats(const float* __restrict__ p){
    float m1[10], m2[55];
#pragma unroll
    for (int i=0;i<10;i++) m1[i]=0.f;
#pragma unroll
    for (int i=0;i<55;i++) m2[i]=0.f;
    int tid = blockIdx.x*blockDim.x + threadIdx.x;
    int nth = gridDim.x*blockDim.x;
    for (int r = tid; r < NK; r += nth){
        int n = r >> 4, k = r & 15;
        const float* pc = p + n*48;
        float c[10];
        c[0]=pc[0];     c[1]=pc[1];     c[2]=pc[2];
        c[3]=pc[3*k];   c[4]=pc[3*k+1]; c[5]=pc[3*k+2];
        c[6]=c[0]-c[3]; c[7]=c[1]-c[4]; c[8]=c[2]-c[5];
        c[9]=sqrtf(c[6]*c[6]+c[7]*c[7]+c[8]*c[8]);
        int t = 0;
#pragma unroll
        for (int a=0;a<10;a++){
            m1[a] += c[a];
#pragma unroll
            for (int b=a;b<10;b++) m2[t++] += c[a]*c[b];
        }
    }
#pragma unroll
    for (int off=16; off>0; off>>=1){
#pragma unroll
        for (int i=0;i<10;i++) m1[i] += __shfl_down_sync(0xffffffffu, m1[i], off);
#pragma unroll
        for (int i=0;i<55;i++) m2[i] += __shfl_down_sync(0xffffffffu, m2[i], off);
    }
    if ((threadIdx.x & 31) == 0){
#pragma unroll
        for (int i=0;i<10;i++) atomicAdd(&g_M1[i], m1[i]);
#pragma unroll
        for (int i=0;i<55;i++) atomicAdd(&g_M2[i], m2[i]);
    }
}

// ---------------- K2: fold BN1 into w1 (exact analytic moments) ----------
__global__ void k_fold(const float* __restrict__ w1, const float* __restrict__ b1,
                       const float* __restrict__ g1, const float* __restrict__ be1){
    int d = threadIdx.x;   // 128 threads
    const double invNK = 1.0 / (double)NK;
    double wv[10];
#pragma unroll
    for (int c=0;c<10;c++) wv[c] = (double)w1[c*128 + d];
    double m = 0.0;
#pragma unroll
    for (int c=0;c<10;c++) m += ((double)g_M1[c]*invNK) * wv[c];
    double q = 0.0;
    int t = 0;
#pragma unroll
    for (int a=0;a<10;a++){
#pragma unroll
        for (int b=a;b<10;b++){
            double s2 = (double)g_M2[t++] * invNK;
            double term = s2 * wv[a] * wv[b];
            q += (a==b) ? term : 2.0*term;
        }
    }
    double var = q - m*m;                    // b1 cancels exactly
    double a1  = (double)g1[d] / sqrt(var + 1e-5);
    g_c1[d] = (float)((double)be1[d] - m*a1);
#pragma unroll
    for (int c=0;c<10;c++) g_w1p[c*128 + d] = (float)(wv[c]*a1);
    (void)b1;
}

// ---------------- K3: fused main kernel ----------------------------------
// smem layout (floats)
#define SM_W1P 0
#define SM_C1  1280
#define SM_B2  1408
#define SM_BO  1472
#define SM_W2  1536
#define SM_WS  9728
#define SM_WO  26112
#define SM_BASE 34304
#define SUBSZ 4672
// per sub-block: h[0..2047] px[2048..4095] cc[4096..4287] fx[4288..4415]
//                ob[4416..4543] s2[4544..4607] ss2[4608..4671]
#define SMEM_FLOATS (SM_BASE + 4*SUBSZ)   // 52992 floats = 211968 B

__global__ void __launch_bounds__(512,1) k_main(
    const float* __restrict__ p, const float* __restrict__ x,
    const float* __restrict__ w2, const float* __restrict__ b2,
    const float* __restrict__ ws, const float* __restrict__ wo,
    const float* __restrict__ bo, float* __restrict__ out)
{
    extern __shared__ float sm[];
    int tid = threadIdx.x;
    int s = tid >> 7;        // sub-block 0..3 (one point each)
    int u = tid & 127;
    float* hS  = sm + SM_BASE + s*SUBSZ;
    float* pxS = hS + 2048;
    float* ccS = hS + 4096;
    float* fxS = hS + 4288;
    float* obS = hS + 4416;
    float* s2S = hS + 4544;
    float* ss2S= hS + 4608;

    for (int i = tid; i < 1280;  i += 512) sm[SM_W1P+i] = g_w1p[i];
    for (int i = tid; i < 128;   i += 512) sm[SM_C1+i]  = g_c1[i];
    if (tid < 64){ sm[SM_B2+tid] = b2[tid]; sm[SM_BO+tid] = bo[tid]; }
    for (int i = tid; i < 8192;  i += 512) sm[SM_W2+i] = w2[i];
    for (int i = tid; i < 16384; i += 512) sm[SM_WS+i] = ws[i];
    for (int i = tid; i < 8192;  i += 512) sm[SM_WO+i] = wo[i];
    if (u < 64){ s2S[u]=0.f; ss2S[u]=0.f; }
    __syncthreads();

    const float* w2s = sm + SM_W2;
    const float* wss = sm + SM_WS;
    const float* wos = sm + SM_WO;

    for (int g = blockIdx.x; g < Nn/4; g += gridDim.x){
        int n = g*4 + s;

        // stage x into px[:,64:128]
        const float4* xv = (const float4*)(x + (size_t)n*1024);
#pragma unroll
        for (int f = 0; f < 2; f++){
            int fi = u + f*128;
            int k = fi >> 4, j4 = fi & 15;
            *(float4*)&pxS[k*128 + 64 + 4*j4] = xv[fi];
        }
        if (u < 48) obS[u] = p[n*48 + u];
        __syncthreads();
        if (u < 16){
            int k = u;
            float cx=obS[0], cy=obS[1], cz=obS[2];
            float qx=obS[3*k], qy=obS[3*k+1], qz=obS[3*k+2];
            float dx=cx-qx, dy=cy-qy, dz=cz-qz;
            float* c = ccS + 12*k;
            c[0]=cx;c[1]=cy;c[2]=cz;c[3]=qx;c[4]=qy;c[5]=qz;
            c[6]=dx;c[7]=dy;c[8]=dz;
            c[9]=sqrtf(dx*dx+dy*dy+dz*dz);
        }
        __syncthreads();

        // h = relu(concat @ w1' + c1)   (BN1 pre-folded)
        {
            float w[10];
#pragma unroll
            for (int c=0;c<10;c++) w[c] = sm[SM_W1P + c*128 + u];
            float cl = sm[SM_C1 + u];
#pragma unroll
            for (int k=0;k<16;k++){
                const float* cr = ccS + 12*k;
                float acc = cl;
#pragma unroll
                for (int c=0;c<10;c++) acc = fmaf(cr[c], w[c], acc);
                hS[k*128 + u] = fmaxf(acc, 0.f);
            }
        }
        __syncthreads();

        // p_c = h @ w2 + b2  -> px[:,0:64]   (f32x2 packed over d-pairs)
        {
            int e = u & 63, kh = u >> 6;
            ull acc[8];
#pragma unroll
            for (int i=0;i<8;i++) acc[i]=0ull;
            const float* hrow = hS + kh*8*128;
            for (int dp=0; dp<64; dp++){
                ull w = pk2(w2s[(2*dp)*64 + e], w2s[(2*dp+1)*64 + e]);
#pragma unroll
                for (int kk=0;kk<8;kk++){
                    ull hp = *(const ull*)(hrow + kk*128 + 2*dp);
                    ffma2(acc[kk], hp, w);
                }
            }
            float bb = sm[SM_B2 + e];
#pragma unroll
            for (int kk=0;kk<8;kk++){
                float2 a = upk2(acc[kk]);
                pxS[(kh*8+kk)*128 + e] = a.x + a.y + bb;
            }
        }
        __syncthreads();

        // logits = px @ ws  -> reuse hS     (f32x2 over c-pairs, 2 e-cols/thread)
        {
            int e0 = u & 63, kh = u >> 6;
            ull acc[16];
#pragma unroll
            for (int i=0;i<16;i++) acc[i]=0ull;
            const float* prow = pxS + kh*8*128;
            for (int cp=0; cp<64; cp++){
                ull w0 = pk2(wss[(2*cp)*128 + e0],      wss[(2*cp+1)*128 + e0]);
                ull w1v= pk2(wss[(2*cp)*128 + e0 + 64], wss[(2*cp+1)*128 + e0 + 64]);
#pragma unroll
                for (int kk=0;kk<8;kk++){
                    ull pp = *(const ull*)(prow + kk*128 + 2*cp);
                    ffma2(acc[kk],   pp, w0);
                    ffma2(acc[8+kk], pp, w1v);
                }
            }
#pragma unroll
            for (int kk=0;kk<8;kk++){
                float2 a = upk2(acc[kk]);
                float2 b = upk2(acc[8+kk]);
                hS[(kh*8+kk)*128 + e0]      = a.x + a.y;
                hS[(kh*8+kk)*128 + e0 + 64] = b.x + b.y;
            }
        }
        __syncthreads();

        // softmax over k (thread-local per channel) + weighted pool
        {
            float l[16];
#pragma unroll
            for (int k=0;k<16;k++) l[k] = hS[k*128 + u];
            float m = l[0];
#pragma unroll
            for (int k=1;k<16;k++) m = fmaxf(m, l[k]);
            float sumv = 0.f;
#pragma unroll
            for (int k=0;k<16;k++){ l[k] = __expf(l[k]-m); sumv += l[k]; }
            float f = 0.f;
#pragma unroll
            for (int k=0;k<16;k++) f = fmaf(l[k], pxS[k*128+u], f);
            fxS[u] = f / sumv;
        }
        __syncthreads();

        // out = feat @ wo + bo  (split-e reduction)
        {
            int j = u & 63, eh = u >> 6;
            float acc = 0.f;
#pragma unroll 8
            for (int e2=0;e2<64;e2++){
                int e = eh*64 + e2;
                acc = fmaf(fxS[e], wos[e*64 + j], acc);
            }
            obS[eh*64 + j] = acc;
        }
        __syncthreads();
        if (u < 64){
            float v = obS[u] + obS[64+u] + sm[SM_BO+u];
            out[(size_t)n*64 + u] = v;
            s2S[u] += v;
            ss2S[u] += v*v;
        }
        __syncthreads();
    }
    if (tid < 64){
        float a=0.f, b=0.f;
#pragma unroll
        for (int si=0; si<4; si++){
            a += sm[SM_BASE + si*SUBSZ + 4544 + tid];
            b += sm[SM_BASE + si*SUBSZ + 4608 + tid];
        }
        atomicAdd(&g_sum2[tid], a);
        atomicAdd(&g_sumsq2[tid], b);
    }
}

// ---------------- K4: finalize BN2 constants ------------------------------
__global__ void k_fin(const float* __restrict__ g2, const float* __restrict__ be2){
    int j = threadIdx.x; // 64
    double inv = 1.0 / (double)Nn;
    double mu  = (double)g_sum2[j] * inv;
    double var = (double)g_sumsq2[j] * inv - mu*mu;
    double a2  = (double)g2[j] / sqrt(var + 1e-5);
    g_a2[j] = (float)a2;
    g_c2[j] = (float)((double)be2[j] - mu*a2);
}

// ---------------- K5: in-place BN2 + relu ---------------------------------
__global__ void k_norm(float* __restrict__ out){
    __shared__ float a2s[64], c2s[64];
    if (threadIdx.x < 64){ a2s[threadIdx.x] = g_a2[threadIdx.x]; c2s[threadIdx.x] = g_c2[threadIdx.x]; }
    __syncthreads();
    const int nq = Nn*64/4;
    float4* o4 = (float4*)out;
    for (int f = blockIdx.x*blockDim.x + threadIdx.x; f < nq; f += gridDim.x*blockDim.x){
        float4 v = o4[f];
        int j = (f*4) & 63;
        v.x = fmaxf(fmaf(v.x, a2s[j],   c2s[j]),   0.f);
        v.y = fmaxf(fmaf(v.y, a2s[j+1], c2s[j+1]), 0.f);
        v.z = fmaxf(fmaf(v.z, a2s[j+2], c2s[j+2]), 0.f);
        v.w = fmaxf(fmaf(v.w, a2s[j+3], c2s[j+3]), 0.f);
        o4[f] = v;
    }
}

// ---------------- launch ---------------------------------------------------
extern "C" void kernel_launch(void* const* d_in, const int* in_sizes, int n_in,
                              void* d_out, int out_size){
    const float* p   = (const float*)d_in[0];
    const float* x   = (const float*)d_in[1];
    const float* w1  = (const float*)d_in[2];
    const float* b1  = (const float*)d_in[3];
    const float* g1  = (const float*)d_in[4];
    const float* be1 = (const float*)d_in[5];
    const float* w2  = (const float*)d_in[6];
    const float* b2  = (const float*)d_in[7];
    const float* ws  = (const float*)d_in[8];
    const float* wo  = (const float*)d_in[9];
    const float* bo  = (const float*)d_in[10];
    const float* g2  = (const float*)d_in[11];
    const float* be2 = (const float*)d_in[12];
    float* out = (float*)d_out;
    (void)in_sizes; (void)n_in; (void)out_size;

    cudaFuncSetAttribute(k_main, cudaFuncAttributeMaxDynamicSharedMemorySize,
                         SMEM_FLOATS*4);

    k_zero<<<1,64>>>();
    k_stats<<<256,256>>>(p);
    k_fold<<<1,128>>>(w1,b1,g1,be1);
    k_main<<<304,512,SMEM_FLOATS*4>>>(p,x,w2,b2,ws,wo,bo,out);
    k_fin<<<1,64>>>(g2,be2);
    k_norm<<<2048,256>>>(out);
}

// round 5
// speedup vs baseline: 1.3672x; 1.3653x over previous
#include <cuda_runtime.h>
typedef unsigned int u32;

#define Nn 65536
#define NK (Nn*16)
#define NTILES (Nn/8)
#define NT 256
#define GRID_MAIN 148

// ---- float offsets in dynamic smem ----
#define F_ACT   0          // 128 x 132 A-tile (h, then px), tf32 bits as float
#define F_W2F   16896      // w2 fragments: 16K x 8nt x 32lane x 2
#define F_WSF   25088      // ws fragments: 16K x 16nt x 32lane x 2
#define F_WOT   41472      // wo^T [64][132]
#define F_WQ    49920      // 128 x {w3-w6, w4-w7, w5-w8, w9}
#define F_WCB   50432      // 128 x {w0+w6, w1+w7, w2+w8, c1}
#define F_B2    50944
#define F_BO    51008
#define F_PSM   51072      // 8x48 p staging
#define F_PROW  51456      // 128 x {qx,qy,qz,dist}
#define F_BASE  51968      // 8 x 128
#define F_FEAT  52992      // 8 x 128
#define F_BNS   54016
#define F_BNQ   54080
#define F_TOTAL 54144
#define SMEM_BYTES (F_TOTAL*4)

__device__ __forceinline__ float to_tf32(float x){
    float r; asm("cvt.rna.tf32.f32 %0, %1;":"=f"(r):"f"(x)); return r;
}
__device__ __forceinline__ void mma_tf32(float* d, u32 a0, u32 a1, u32 a2, u32 a3,
                                         u32 b0, u32 b1){
    asm volatile("mma.sync.aligned.m16n8k8.row.col.f32.tf32.tf32.f32 "
        "{%0,%1,%2,%3}, {%4,%5,%6,%7}, {%8,%9}, {%0,%1,%2,%3};"
        : "+f"(d[0]),"+f"(d[1]),"+f"(d[2]),"+f"(d[3])
        : "r"(a0),"r"(a1),"r"(a2),"r"(a3),"r"(b0),"r"(b1));
}

// ---- scratch globals ----
__device__ float g_M1[10], g_M2[55], g_w1p[1280], g_c1[128];
__device__ float g_sum2[64], g_sumsq2[64], g_a2[64], g_c2[64];

__global__ void k_zero(){
    int t = threadIdx.x;
    if (t < 10) g_M1[t]=0.f;
    if (t < 55) g_M2[t]=0.f;
    if (t < 64){ g_sum2[t]=0.f; g_sumsq2[t]=0.f; }
}

__global__ void k_stats(const float* __restrict__ p){
    __shared__ float red[8][65];
    float m1[10], m2[55];
#pragma unroll
    for (int i=0;i<10;i++) m1[i]=0.f;
#pragma unroll
    for (int i=0;i<55;i++) m2[i]=0.f;
    int tid = blockIdx.x*blockDim.x + threadIdx.x, nth = gridDim.x*blockDim.x;
    for (int r = tid; r < NK; r += nth){
        int n = r >> 4, k = r & 15;
        const float* pc = p + n*48;
        float c[10];
        c[0]=pc[0]; c[1]=pc[1]; c[2]=pc[2];
        c[3]=pc[3*k]; c[4]=pc[3*k+1]; c[5]=pc[3*k+2];
        c[6]=c[0]-c[3]; c[7]=c[1]-c[4]; c[8]=c[2]-c[5];
        c[9]=sqrtf(c[6]*c[6]+c[7]*c[7]+c[8]*c[8]);
        int t = 0;
#pragma unroll
        for (int a=0;a<10;a++){
            m1[a] += c[a];
#pragma unroll
            for (int b=a;b<10;b++) m2[t++] += c[a]*c[b];
        }
    }
#pragma unroll
    for (int off=16; off>0; off>>=1){
#pragma unroll
        for (int i=0;i<10;i++) m1[i] += __shfl_down_sync(0xffffffffu, m1[i], off);
#pragma unroll
        for (int i=0;i<55;i++) m2[i] += __shfl_down_sync(0xffffffffu, m2[i], off);
    }
    int wid = threadIdx.x>>5;
    if ((threadIdx.x&31)==0){
#pragma unroll
        for (int i=0;i<10;i++) red[wid][i]=m1[i];
#pragma unroll
        for (int i=0;i<55;i++) red[wid][10+i]=m2[i];
    }
    __syncthreads();
    if (threadIdx.x < 65){
        float a=0.f;
#pragma unroll
        for (int w=0;w<8;w++) a += red[w][threadIdx.x];
        if (threadIdx.x < 10) atomicAdd(&g_M1[threadIdx.x], a);
        else atomicAdd(&g_M2[threadIdx.x-10], a);
    }
}

__global__ void k_fold(const float* __restrict__ w1, const float* __restrict__ g1,
                       const float* __restrict__ be1){
    int d = threadIdx.x;
    const double invNK = 1.0/(double)NK;
    double wv[10];
#pragma unroll
    for (int c=0;c<10;c++) wv[c] = (double)w1[c*128+d];
    double m = 0.0;
#pragma unroll
    for (int c=0;c<10;c++) m += ((double)g_M1[c]*invNK)*wv[c];
    double q = 0.0; int t = 0;
#pragma unroll
    for (int a=0;a<10;a++)
#pragma unroll
        for (int b=a;b<10;b++){
            double s2 = (double)g_M2[t++]*invNK;
            double term = s2*wv[a]*wv[b];
            q += (a==b) ? term : 2.0*term;
        }
    double var = q - m*m;
    double a1 = (double)g1[d] / sqrt(var + 1e-5);
    g_c1[d] = (float)((double)be1[d] - m*a1);
#pragma unroll
    for (int c=0;c<10;c++) g_w1p[c*128+d] = (float)(wv[c]*a1);
}

__global__ void __launch_bounds__(NT,1) k_main(
    const float* __restrict__ p, const float* __restrict__ x,
    const float* __restrict__ w2, const float* __restrict__ b2,
    const float* __restrict__ ws, const float* __restrict__ wo,
    const float* __restrict__ bo, float* __restrict__ out)
{
    extern __shared__ float sm[];
    int tid = threadIdx.x, w = tid>>5, lid = tid&31;
    int g = lid>>2, tq = lid&3;

    // ---- stage weights in fragment order ----
    for (int i = tid; i < 4096; i += NT){          // w2: (K,nt,lane) pairs
        int L = i&31, nt = (i>>5)&7, K = i>>8;
        int tt = L&3, gg = L>>2;
        sm[F_W2F + i*2  ] = to_tf32(w2[(K*8+tt  )*64 + nt*8+gg]);
        sm[F_W2F + i*2+1] = to_tf32(w2[(K*8+tt+4)*64 + nt*8+gg]);
    }
    for (int i = tid; i < 8192; i += NT){          // ws: (K,nt,lane) pairs
        int L = i&31, nt = (i>>5)&15, K = i>>9;
        int tt = L&3, gg = L>>2;
        sm[F_WSF + i*2  ] = to_tf32(ws[(K*8+tt  )*128 + nt*8+gg]);
        sm[F_WSF + i*2+1] = to_tf32(ws[(K*8+tt+4)*128 + nt*8+gg]);
    }
    for (int i = tid; i < 8192; i += NT){          // woT[j][e]
        int e = i>>6, j = i&63;
        sm[F_WOT + j*132 + e] = wo[i];
    }
    if (tid < 128){
        int c = tid;
        float w0=g_w1p[c],     w1v=g_w1p[128+c], w2v=g_w1p[256+c];
        float w3=g_w1p[384+c], w4=g_w1p[512+c],  w5=g_w1p[640+c];
        float w6=g_w1p[768+c], w7=g_w1p[896+c],  w8=g_w1p[1024+c];
        float w9=g_w1p[1152+c];
        sm[F_WQ +4*c+0]=w3-w6; sm[F_WQ +4*c+1]=w4-w7; sm[F_WQ +4*c+2]=w5-w8; sm[F_WQ +4*c+3]=w9;
        sm[F_WCB+4*c+0]=w0+w6; sm[F_WCB+4*c+1]=w1v+w7; sm[F_WCB+4*c+2]=w2v+w8; sm[F_WCB+4*c+3]=g_c1[c];
    }
    if (tid < 64){ sm[F_B2+tid]=b2[tid]; sm[F_BO+tid]=bo[tid]; sm[F_BNS+tid]=0.f; sm[F_BNQ+tid]=0.f; }
    __syncthreads();

    float bs = 0.f, bq = 0.f;
    int xrow = tid >> 1, xdh = (tid & 1) * 32;
    int rA0 = (w*16 + g)*132;          // fragment row g of warp's m-tile
    int rA1 = (w*16 + g + 8)*132;      // row g+8

    for (int t = blockIdx.x; t < NTILES; t += gridDim.x){
        // prefetch x (32 floats per thread, own m-tile rows)
        const float4* xp = (const float4*)(x + ((size_t)t*128 + xrow)*64 + xdh);
        float4 xr[8];
#pragma unroll
        for (int i=0;i<8;i++) xr[i] = xp[i];

        if (tid < 96) *(float4*)&sm[F_PSM + tid*4] = *(const float4*)(p + (size_t)t*384 + tid*4);
        __syncthreads();
        if (tid < 128){
            int pt = tid>>4, k = tid&15;
            float cx=sm[F_PSM+pt*48],     cy=sm[F_PSM+pt*48+1],     cz=sm[F_PSM+pt*48+2];
            float qx=sm[F_PSM+pt*48+3*k], qy=sm[F_PSM+pt*48+3*k+1], qz=sm[F_PSM+pt*48+3*k+2];
            float dx=cx-qx, dy=cy-qy, dz=cz-qz;
            sm[F_PROW+4*tid+0]=qx; sm[F_PROW+4*tid+1]=qy; sm[F_PROW+4*tid+2]=qz;
            sm[F_PROW+4*tid+3]=sqrtf(dx*dx+dy*dy+dz*dz);
        }
        for (int idx = tid; idx < 1024; idx += NT){
            int pt = idx>>7, c = idx&127;
            float cx=sm[F_PSM+pt*48], cy=sm[F_PSM+pt*48+1], cz=sm[F_PSM+pt*48+2];
            float4 wb = *(float4*)&sm[F_WCB+4*c];
            sm[F_BASE+idx] = fmaf(cx,wb.x,fmaf(cy,wb.y,fmaf(cz,wb.z,wb.w)));
        }
        __syncthreads();

        // h = relu(folded layer1) -> A tile rows (tf32 bits)
        {
            int c = tid & 127, rh = tid >> 7;
            float4 wq = *(float4*)&sm[F_WQ+4*c];
#pragma unroll 4
            for (int rr = 0; rr < 64; rr++){
                int row = rh*64 + rr;
                float4 pr = *(float4*)&sm[F_PROW+4*row];
                float v = sm[F_BASE + (row>>4)*128 + c];
                v = fmaf(pr.x,wq.x,v); v = fmaf(pr.y,wq.y,v);
                v = fmaf(pr.z,wq.z,v); v = fmaf(pr.w,wq.w,v);
                sm[F_ACT + row*132 + c] = to_tf32(fmaxf(v,0.f));
            }
        }
        __syncthreads();

        // ---- GEMM2: p_c = h @ w2  (warp-private 16x64) ----
        float d2[8][4];
#pragma unroll
        for (int n=0;n<8;n++){ d2[n][0]=0.f; d2[n][1]=0.f; d2[n][2]=0.f; d2[n][3]=0.f; }
#pragma unroll 4
        for (int K=0;K<16;K++){
            const float* ab = &sm[F_ACT + K*8 + tq];
            u32 a0 = __float_as_uint(ab[rA0]);
            u32 a1 = __float_as_uint(ab[rA1]);
            u32 a2 = __float_as_uint(ab[rA0+4]);
            u32 a3 = __float_as_uint(ab[rA1+4]);
#pragma unroll
            for (int n=0;n<8;n++){
                float2 bv = *(float2*)&sm[F_W2F + ((K*8+n)*32 + lid)*2];
                mma_tf32(d2[n], a0,a1,a2,a3, __float_as_uint(bv.x), __float_as_uint(bv.y));
            }
        }
        // write px = [p_c + b2 | x] into own rows (tf32)
#pragma unroll
        for (int n=0;n<8;n++){
            int c0 = n*8 + 2*tq;
            float ba = sm[F_B2+c0], bb = sm[F_B2+c0+1];
            float2 lo, hi;
            lo.x = to_tf32(d2[n][0]+ba); lo.y = to_tf32(d2[n][1]+bb);
            hi.x = to_tf32(d2[n][2]+ba); hi.y = to_tf32(d2[n][3]+bb);
            *(float2*)&sm[F_ACT + rA0 + c0] = lo;
            *(float2*)&sm[F_ACT + rA1 + c0] = hi;
        }
#pragma unroll
        for (int i=0;i<8;i++){
            float4 v = xr[i];
            float4 wv;
            wv.x=to_tf32(v.x); wv.y=to_tf32(v.y); wv.z=to_tf32(v.z); wv.w=to_tf32(v.w);
            *(float4*)&sm[F_ACT + xrow*132 + 64 + xdh + i*4] = wv;
        }
        __syncwarp();

        // ---- GEMM3: logits = px @ ws  (warp-private 16x128) ----
        float d3[16][4];
#pragma unroll
        for (int n=0;n<16;n++){ d3[n][0]=0.f; d3[n][1]=0.f; d3[n][2]=0.f; d3[n][3]=0.f; }
#pragma unroll 2
        for (int K=0;K<16;K++){
            const float* ab = &sm[F_ACT + K*8 + tq];
            u32 a0 = __float_as_uint(ab[rA0]);
            u32 a1 = __float_as_uint(ab[rA1]);
            u32 a2 = __float_as_uint(ab[rA0+4]);
            u32 a3 = __float_as_uint(ab[rA1+4]);
#pragma unroll
            for (int n=0;n<16;n++){
                float2 bv = *(float2*)&sm[F_WSF + ((K*16+n)*32 + lid)*2];
                mma_tf32(d3[n], a0,a1,a2,a3, __float_as_uint(bv.x), __float_as_uint(bv.y));
            }
        }

        // ---- softmax over k (rows of the point) + pooled feat ----
#pragma unroll
        for (int n=0;n<16;n++){
            int c0 = n*8 + 2*tq;
            float e0 = __expf(d3[n][0]), e1 = __expf(d3[n][1]);
            float e2 = __expf(d3[n][2]), e3 = __expf(d3[n][3]);
            float2 plo = *(float2*)&sm[F_ACT + rA0 + c0];
            float2 phi = *(float2*)&sm[F_ACT + rA1 + c0];
            float se = e0 + e2, so = e1 + e3;
            float ve = fmaf(e0, plo.x, e2*phi.x);
            float vo = fmaf(e1, plo.y, e3*phi.y);
#pragma unroll
            for (int m=4;m<32;m<<=1){
                se += __shfl_xor_sync(0xffffffffu, se, m);
                so += __shfl_xor_sync(0xffffffffu, so, m);
                ve += __shfl_xor_sync(0xffffffffu, ve, m);
                vo += __shfl_xor_sync(0xffffffffu, vo, m);
            }
            if (lid < 4){
                float2 f; f.x = ve/se; f.y = vo/so;
                *(float2*)&sm[F_FEAT + w*128 + c0] = f;
            }
        }
        __syncthreads();

        // ---- out = feat @ wo + bo, BN2 partials ----
        {
            int j = tid & 63, qh = tid >> 6;
            int pt0 = qh*2;
            float a0 = 0.f, a1 = 0.f;
#pragma unroll 8
            for (int e=0;e<128;e+=4){
                float4 wv = *(float4*)&sm[F_WOT + j*132 + e];
                float4 f0 = *(float4*)&sm[F_FEAT + pt0*128 + e];
                float4 f1 = *(float4*)&sm[F_FEAT + (pt0+1)*128 + e];
                a0 = fmaf(f0.x,wv.x,fmaf(f0.y,wv.y,fmaf(f0.z,wv.z,fmaf(f0.w,wv.w,a0))));
                a1 = fmaf(f1.x,wv.x,fmaf(f1.y,wv.y,fmaf(f1.z,wv.z,fmaf(f1.w,wv.w,a1))));
            }
            float bb = sm[F_BO+j];
            float v0 = a0 + bb, v1 = a1 + bb;
            out[((size_t)t*8 + pt0    )*64 + j] = v0;
            out[((size_t)t*8 + pt0 + 1)*64 + j] = v1;
            bs += v0 + v1;
            bq += v0*v0 + v1*v1;
        }
        __syncthreads();
    }

    atomicAdd(&sm[F_BNS + (tid & 63)], bs);
    atomicAdd(&sm[F_BNQ + (tid & 63)], bq);
    __syncthreads();
    if (tid < 64){
        atomicAdd(&g_sum2[tid],   sm[F_BNS+tid]);
        atomicAdd(&g_sumsq2[tid], sm[F_BNQ+tid]);
    }
}

__global__ void k_fin(const float* __restrict__ g2, const float* __restrict__ be2){
    int j = threadIdx.x;
    double inv = 1.0/(double)Nn;
    double mu  = (double)g_sum2[j]*inv;
    double var = (double)g_sumsq2[j]*inv - mu*mu;
    double a2  = (double)g2[j] / sqrt(var + 1e-5);
    g_a2[j] = (float)a2;
    g_c2[j] = (float)((double)be2[j] - mu*a2);
}

__global__ void k_norm(float* __restrict__ out){
    __shared__ float a2s[64], c2s[64];
    if (threadIdx.x < 64){ a2s[threadIdx.x]=g_a2[threadIdx.x]; c2s[threadIdx.x]=g_c2[threadIdx.x]; }
    __syncthreads();
    const int nq = Nn*64/4;
    float4* o4 = (float4*)out;
    for (int f = blockIdx.x*blockDim.x + threadIdx.x; f < nq; f += gridDim.x*blockDim.x){
        float4 v = o4[f];
        int j = (f*4) & 63;
        v.x = fmaxf(fmaf(v.x, a2s[j],   c2s[j]),   0.f);
        v.y = fmaxf(fmaf(v.y, a2s[j+1], c2s[j+1]), 0.f);
        v.z = fmaxf(fmaf(v.z, a2s[j+2], c2s[j+2]), 0.f);
        v.w = fmaxf(fmaf(v.w, a2s[j+3], c2s[j+3]), 0.f);
        o4[f] = v;
    }
}

extern "C" void kernel_launch(void* const* d_in, const int* in_sizes, int n_in,
                              void* d_out, int out_size){
    const float* p   = (const float*)d_in[0];
    const float* x   = (const float*)d_in[1];
    const float* w1  = (const float*)d_in[2];
    const float* g1  = (const float*)d_in[4];
    const float* be1 = (const float*)d_in[5];
    const float* w2  = (const float*)d_in[6];
    const float* b2  = (const float*)d_in[7];
    const float* ws  = (const float*)d_in[8];
    const float* wo  = (const float*)d_in[9];
    const float* bo  = (const float*)d_in[10];
    const float* g2  = (const float*)d_in[11];
    const float* be2 = (const float*)d_in[12];
    float* out = (float*)d_out;
    (void)in_sizes; (void)n_in; (void)out_size;

    cudaFuncSetAttribute(k_main, cudaFuncAttributeMaxDynamicSharedMemorySize, SMEM_BYTES);

    k_zero<<<1,64>>>();
    k_stats<<<256,256>>>(p);
    k_fold<<<1,128>>>(w1,g1,be1);
    k_main<<<GRID_MAIN,NT,SMEM_BYTES>>>(p,x,w2,b2,ws,wo,bo,out);
    k_fin<<<1,64>>>(g2,be2);
    k_norm<<<2048,256>>>(out);
}

// round 6
// speedup vs baseline: 3.0434x; 2.2261x over previous
#include <cuda_runtime.h>
typedef unsigned int u32;

#define Nn 65536
#define NK (Nn*16)
#define NTILES (Nn/8)
#define NT 512
#define GRID_MAIN 148

// ---- float offsets in dynamic smem ----
#define F_ACT   0          // 128 x 132 A-tile (h, then px)
#define F_A1H   16896      // 128 x 12 layer1-A hi
#define F_A1L   18432      // 128 x 12 layer1-A lo
#define F_W1FH  19968      // layer1 B frags hi: 8n2 x 32 x 4
#define F_W1FL  20992
#define F_W2F   22016      // w2 frags: 16K x 4n2 x 32 x 4
#define F_WSF   30208      // ws frags: 16K x 8n2 x 32 x 4
#define F_WOF   46592      // wo frags: 16K x 8n x 32 x 2
#define F_FEAT  54784      // 8 x 132
#define F_PSM   55840      // 8 x 48
#define F_B2    56224
#define F_BO    56288
#define F_BNS   56352
#define F_BNQ   56416
#define F_TOTAL 56480
#define SMEM_BYTES (F_TOTAL*4)

__device__ __forceinline__ float to_tf32(float x){
    float r; asm("cvt.rna.tf32.f32 %0, %1;":"=f"(r):"f"(x)); return r;
}
__device__ __forceinline__ void mma4(float* d, u32 a0, u32 a1, u32 a2, u32 a3,
                                     u32 b0, u32 b1){
    asm volatile("mma.sync.aligned.m16n8k8.row.col.f32.tf32.tf32.f32 "
        "{%0,%1,%2,%3}, {%4,%5,%6,%7}, {%8,%9}, {%0,%1,%2,%3};"
        : "+f"(d[0]),"+f"(d[1]),"+f"(d[2]),"+f"(d[3])
        : "r"(a0),"r"(a1),"r"(a2),"r"(a3),"r"(b0),"r"(b1));
}

// ---- scratch globals ----
__device__ float g_M1[10], g_M2[55], g_w1p[1280], g_c1[128];
__device__ float g_sum2[64], g_sumsq2[64], g_a2[64], g_c2[64];

__global__ void k_zero(){
    int t = threadIdx.x;
    if (t < 10) g_M1[t]=0.f;
    if (t < 55) g_M2[t]=0.f;
    if (t < 64){ g_sum2[t]=0.f; g_sumsq2[t]=0.f; }
}

__global__ void k_stats(const float* __restrict__ p){
    __shared__ float red[8][65];
    float m1[10], m2[55];
#pragma unroll
    for (int i=0;i<10;i++) m1[i]=0.f;
#pragma unroll
    for (int i=0;i<55;i++) m2[i]=0.f;
    int tid = blockIdx.x*blockDim.x + threadIdx.x, nth = gridDim.x*blockDim.x;
    for (int r = tid; r < NK; r += nth){
        int n = r >> 4, k = r & 15;
        const float* pc = p + n*48;
        float c[10];
        c[0]=pc[0]; c[1]=pc[1]; c[2]=pc[2];
        c[3]=pc[3*k]; c[4]=pc[3*k+1]; c[5]=pc[3*k+2];
        c[6]=c[0]-c[3]; c[7]=c[1]-c[4]; c[8]=c[2]-c[5];
        c[9]=sqrtf(c[6]*c[6]+c[7]*c[7]+c[8]*c[8]);
        int t = 0;
#pragma unroll
        for (int a=0;a<10;a++){
            m1[a] += c[a];
#pragma unroll
            for (int b=a;b<10;b++) m2[t++] += c[a]*c[b];
        }
    }
#pragma unroll
    for (int off=16; off>0; off>>=1){
#pragma unroll
        for (int i=0;i<10;i++) m1[i] += __shfl_down_sync(0xffffffffu, m1[i], off);
#pragma unroll
        for (int i=0;i<55;i++) m2[i] += __shfl_down_sync(0xffffffffu, m2[i], off);
    }
    int wid = threadIdx.x>>5;
    if ((threadIdx.x&31)==0){
#pragma unroll
        for (int i=0;i<10;i++) red[wid][i]=m1[i];
#pragma unroll
        for (int i=0;i<55;i++) red[wid][10+i]=m2[i];
    }
    __syncthreads();
    if (threadIdx.x < 65){
        float a=0.f;
#pragma unroll
        for (int w=0;w<8;w++) a += red[w][threadIdx.x];
        if (threadIdx.x < 10) atomicAdd(&g_M1[threadIdx.x], a);
        else atomicAdd(&g_M2[threadIdx.x-10], a);
    }
}

__global__ void k_fold(const float* __restrict__ w1, const float* __restrict__ g1,
                       const float* __restrict__ be1){
    int d = threadIdx.x;
    const double invNK = 1.0/(double)NK;
    double wv[10];
#pragma unroll
    for (int c=0;c<10;c++) wv[c] = (double)w1[c*128+d];
    double m = 0.0;
#pragma unroll
    for (int c=0;c<10;c++) m += ((double)g_M1[c]*invNK)*wv[c];
    double q = 0.0; int t = 0;
#pragma unroll
    for (int a=0;a<10;a++)
#pragma unroll
        for (int b=a;b<10;b++){
            double s2 = (double)g_M2[t++]*invNK;
            double term = s2*wv[a]*wv[b];
            q += (a==b) ? term : 2.0*term;
        }
    double var = q - m*m;
    double a1 = (double)g1[d] / sqrt(var + 1e-5);
    g_c1[d] = (float)((double)be1[d] - m*a1);
#pragma unroll
    for (int c=0;c<10;c++) g_w1p[c*128+d] = (float)(wv[c]*a1);
}

// W8 row r (0..7), col c: layer-1 folded weights in A1 basis
__device__ __forceinline__ float w8row(int r, int c){
    switch(r){
        case 0: return g_w1p[384+c] - g_w1p[768+c];
        case 1: return g_w1p[512+c] - g_w1p[896+c];
        case 2: return g_w1p[640+c] - g_w1p[1024+c];
        case 3: return g_w1p[1152+c];
        case 4: return g_w1p[c]     + g_w1p[768+c];
        case 5: return g_w1p[128+c] + g_w1p[896+c];
        case 6: return g_w1p[256+c] + g_w1p[1024+c];
        default: return g_c1[c];
    }
}

__global__ void __launch_bounds__(NT,1) k_main(
    const float* __restrict__ p, const float* __restrict__ x,
    const float* __restrict__ w2, const float* __restrict__ b2,
    const float* __restrict__ ws, const float* __restrict__ wo,
    const float* __restrict__ bo, float* __restrict__ out)
{
    extern __shared__ float sm[];
    int tid = threadIdx.x, w = tid>>5, lid = tid&31;
    int g = lid>>2, tq = lid&3;
    int wl = w & 7;                 // point index / row-block
    int rA = wl*16;                 // warp's A rows base
    bool lowhalf = (w < 8);

    // ---- stage weight fragments ----
    for (int i = tid; i < 2048; i += NT){        // w2: [K][n2(4)][lid] float4
        int l2 = i&31, n2 = (i>>5)&3, K = i>>7;
        int g2 = l2>>2, t2 = l2&3;
        int r0 = K*8+t2, r1 = r0+4, c0 = n2*16+g2;
        float4 v;
        v.x = to_tf32(w2[r0*64+c0]);   v.y = to_tf32(w2[r1*64+c0]);
        v.z = to_tf32(w2[r0*64+c0+8]); v.w = to_tf32(w2[r1*64+c0+8]);
        *(float4*)&sm[F_W2F + i*4] = v;
    }
    for (int i = tid; i < 4096; i += NT){        // ws: [K][n2(8)][lid] float4
        int l2 = i&31, n2 = (i>>5)&7, K = i>>8;
        int g2 = l2>>2, t2 = l2&3;
        int r0 = K*8+t2, r1 = r0+4, c0 = n2*16+g2;
        float4 v;
        v.x = to_tf32(ws[r0*128+c0]);   v.y = to_tf32(ws[r1*128+c0]);
        v.z = to_tf32(ws[r0*128+c0+8]); v.w = to_tf32(ws[r1*128+c0+8]);
        *(float4*)&sm[F_WSF + i*4] = v;
    }
    for (int i = tid; i < 4096; i += NT){        // wo: [K][n(8)][lid] float2
        int l2 = i&31, n = (i>>5)&7, K = i>>8;
        int g2 = l2>>2, t2 = l2&3;
        float2 v;
        v.x = to_tf32(wo[(K*8+t2  )*64 + n*8+g2]);
        v.y = to_tf32(wo[(K*8+t2+4)*64 + n*8+g2]);
        *(float2*)&sm[F_WOF + i*2] = v;
    }
    if (tid < 256){                              // layer1 B frags, hi/lo split
        int i = tid, l2 = i&31, n2 = (i>>5)&7;
        int g2 = l2>>2, t2 = l2&3;
#pragma unroll
        for (int j=0;j<2;j++){
            int c = (2*n2+j)*8 + g2;
            float v0 = w8row(t2,   c);
            float v1 = w8row(t2+4, c);
            float h0 = to_tf32(v0), h1 = to_tf32(v1);
            sm[F_W1FH + (n2*32+l2)*4 + 2*j  ] = h0;
            sm[F_W1FH + (n2*32+l2)*4 + 2*j+1] = h1;
            sm[F_W1FL + (n2*32+l2)*4 + 2*j  ] = to_tf32(v0-h0);
            sm[F_W1FL + (n2*32+l2)*4 + 2*j+1] = to_tf32(v1-h1);
        }
    }
    if (tid < 64){ sm[F_B2+tid]=b2[tid]; sm[F_BO+tid]=bo[tid]; sm[F_BNS+tid]=0.f; sm[F_BNQ+tid]=0.f; }
    __syncthreads();

    float bs0=0.f, bs1=0.f, bq0=0.f, bq1=0.f;
    int xrow = wl*16 + (lid>>1);
    int xcol = (lowhalf?0:32) + (lid&1)*16;

    for (int t = blockIdx.x; t < NTILES; t += gridDim.x){
        // prefetch x (16 floats / thread)
        const float4* xp = (const float4*)(x + ((size_t)t*128 + xrow)*64 + xcol);
        float4 xr[4];
#pragma unroll
        for (int i=0;i<4;i++) xr[i] = xp[i];

        if (tid < 96) *(float4*)&sm[F_PSM + tid*4] = *(const float4*)(p + (size_t)t*384 + tid*4);
        __syncthreads();

        // build layer1 A (hi/lo) : row = (pt,k), cols [qx,qy,qz,dist,cx,cy,cz,1]
        if (tid < 128){
            int pt = tid>>4, k = tid&15;
            float cx=sm[F_PSM+pt*48],     cy=sm[F_PSM+pt*48+1],     cz=sm[F_PSM+pt*48+2];
            float qx=sm[F_PSM+pt*48+3*k], qy=sm[F_PSM+pt*48+3*k+1], qz=sm[F_PSM+pt*48+3*k+2];
            float dx=cx-qx, dy=cy-qy, dz=cz-qz;
            float ds = sqrtf(dx*dx+dy*dy+dz*dz);
            float vv[8] = {qx,qy,qz,ds,cx,cy,cz,1.f};
#pragma unroll
            for (int c=0;c<8;c++){
                float hi = to_tf32(vv[c]);
                sm[F_A1H + tid*12 + c] = hi;
                sm[F_A1L + tid*12 + c] = to_tf32(vv[c]-hi);
            }
        }
        __syncthreads();

        // ---- GEMM1 (K=8, split tf32): h = relu(A1 @ W8) -> ACT ----
        {
            u32 ah0 = __float_as_uint(sm[F_A1H + (rA+g  )*12 + tq]);
            u32 ah1 = __float_as_uint(sm[F_A1H + (rA+g+8)*12 + tq]);
            u32 ah2 = __float_as_uint(sm[F_A1H + (rA+g  )*12 + tq+4]);
            u32 ah3 = __float_as_uint(sm[F_A1H + (rA+g+8)*12 + tq+4]);
            u32 al0 = __float_as_uint(sm[F_A1L + (rA+g  )*12 + tq]);
            u32 al1 = __float_as_uint(sm[F_A1L + (rA+g+8)*12 + tq]);
            u32 al2 = __float_as_uint(sm[F_A1L + (rA+g  )*12 + tq+4]);
            u32 al3 = __float_as_uint(sm[F_A1L + (rA+g+8)*12 + tq+4]);
            int n2b = lowhalf ? 0 : 4;
#pragma unroll
            for (int j=0;j<4;j++){
                int n2g = n2b + j;
                float4 bh = *(float4*)&sm[F_W1FH + (n2g*32+lid)*4];
                float4 bl = *(float4*)&sm[F_W1FL + (n2g*32+lid)*4];
#pragma unroll
                for (int par=0;par<2;par++){
                    float d[4] = {0.f,0.f,0.f,0.f};
                    u32 b0 = __float_as_uint(par? bh.z : bh.x);
                    u32 b1 = __float_as_uint(par? bh.w : bh.y);
                    u32 c0u= __float_as_uint(par? bl.z : bl.x);
                    u32 c1u= __float_as_uint(par? bl.w : bl.y);
                    mma4(d, ah0,ah1,ah2,ah3, b0,b1);
                    mma4(d, al0,al1,al2,al3, b0,b1);
                    mma4(d, ah0,ah1,ah2,ah3, c0u,c1u);
                    int c0 = (n2g*2+par)*8 + 2*tq;
                    float2 lo, hi;
                    lo.x = to_tf32(fmaxf(d[0],0.f)); lo.y = to_tf32(fmaxf(d[1],0.f));
                    hi.x = to_tf32(fmaxf(d[2],0.f)); hi.y = to_tf32(fmaxf(d[3],0.f));
                    *(float2*)&sm[F_ACT + (rA+g  )*132 + c0] = lo;
                    *(float2*)&sm[F_ACT + (rA+g+8)*132 + c0] = hi;
                }
            }
        }
        __syncthreads();

        // ---- GEMM2: p_c = h @ w2 (4 n-tiles per warp) ----
        float d2[4][4];
#pragma unroll
        for (int n=0;n<4;n++){ d2[n][0]=0.f; d2[n][1]=0.f; d2[n][2]=0.f; d2[n][3]=0.f; }
        {
            int n2b = lowhalf ? 0 : 2;
#pragma unroll 4
            for (int K=0;K<16;K++){
                const float* ar = &sm[F_ACT + K*8 + tq];
                u32 a0 = __float_as_uint(ar[(rA+g  )*132]);
                u32 a1 = __float_as_uint(ar[(rA+g+8)*132]);
                u32 a2 = __float_as_uint(ar[(rA+g  )*132+4]);
                u32 a3 = __float_as_uint(ar[(rA+g+8)*132+4]);
                float4 b0 = *(float4*)&sm[F_W2F + ((K*4+n2b  )*32+lid)*4];
                float4 b1 = *(float4*)&sm[F_W2F + ((K*4+n2b+1)*32+lid)*4];
                mma4(d2[0], a0,a1,a2,a3, __float_as_uint(b0.x), __float_as_uint(b0.y));
                mma4(d2[1], a0,a1,a2,a3, __float_as_uint(b0.z), __float_as_uint(b0.w));
                mma4(d2[2], a0,a1,a2,a3, __float_as_uint(b1.x), __float_as_uint(b1.y));
                mma4(d2[3], a0,a1,a2,a3, __float_as_uint(b1.z), __float_as_uint(b1.w));
            }
        }
        // write px = [p_c + b2 | x]
        {
            int nb = lowhalf ? 0 : 4;
#pragma unroll
            for (int n=0;n<4;n++){
                int c0 = (nb+n)*8 + 2*tq;
                float ba = sm[F_B2+c0], bb = sm[F_B2+c0+1];
                float2 lo, hi;
                lo.x = to_tf32(d2[n][0]+ba); lo.y = to_tf32(d2[n][1]+bb);
                hi.x = to_tf32(d2[n][2]+ba); hi.y = to_tf32(d2[n][3]+bb);
                *(float2*)&sm[F_ACT + (rA+g  )*132 + c0] = lo;
                *(float2*)&sm[F_ACT + (rA+g+8)*132 + c0] = hi;
            }
#pragma unroll
            for (int i=0;i<4;i++){
                float4 v = xr[i], wv;
                wv.x=to_tf32(v.x); wv.y=to_tf32(v.y); wv.z=to_tf32(v.z); wv.w=to_tf32(v.w);
                *(float4*)&sm[F_ACT + xrow*132 + 64 + xcol + i*4] = wv;
            }
        }
        __syncthreads();

        // ---- GEMM3: logits = px @ ws (8 n-tiles per warp) ----
        float d3[8][4];
#pragma unroll
        for (int n=0;n<8;n++){ d3[n][0]=0.f; d3[n][1]=0.f; d3[n][2]=0.f; d3[n][3]=0.f; }
        {
            int n2b = lowhalf ? 0 : 4;
#pragma unroll 2
            for (int K=0;K<16;K++){
                const float* ar = &sm[F_ACT + K*8 + tq];
                u32 a0 = __float_as_uint(ar[(rA+g  )*132]);
                u32 a1 = __float_as_uint(ar[(rA+g+8)*132]);
                u32 a2 = __float_as_uint(ar[(rA+g  )*132+4]);
                u32 a3 = __float_as_uint(ar[(rA+g+8)*132+4]);
#pragma unroll
                for (int j=0;j<4;j++){
                    float4 bv = *(float4*)&sm[F_WSF + ((K*8+n2b+j)*32+lid)*4];
                    mma4(d3[2*j  ], a0,a1,a2,a3, __float_as_uint(bv.x), __float_as_uint(bv.y));
                    mma4(d3[2*j+1], a0,a1,a2,a3, __float_as_uint(bv.z), __float_as_uint(bv.w));
                }
            }
        }

        // ---- softmax over k + pooled feat (warp covers its 64 e-cols) ----
        {
            int nb = lowhalf ? 0 : 8;
#pragma unroll
            for (int nl=0; nl<8; nl++){
                int c0 = (nb+nl)*8 + 2*tq;
                float e0 = __expf(d3[nl][0]), e1 = __expf(d3[nl][1]);
                float e2 = __expf(d3[nl][2]), e3 = __expf(d3[nl][3]);
                float2 plo = *(float2*)&sm[F_ACT + (rA+g  )*132 + c0];
                float2 phi = *(float2*)&sm[F_ACT + (rA+g+8)*132 + c0];
                float se = e0+e2, so = e1+e3;
                float ve = fmaf(e0, plo.x, e2*phi.x);
                float vo = fmaf(e1, plo.y, e3*phi.y);
#pragma unroll
                for (int m=4;m<32;m<<=1){
                    se += __shfl_xor_sync(0xffffffffu, se, m);
                    so += __shfl_xor_sync(0xffffffffu, so, m);
                    ve += __shfl_xor_sync(0xffffffffu, ve, m);
                    vo += __shfl_xor_sync(0xffffffffu, vo, m);
                }
                if (lid < 4){
                    float2 f; f.x = ve/se; f.y = vo/so;
                    *(float2*)&sm[F_FEAT + wl*132 + c0] = f;
                }
            }
        }
        __syncthreads();

        // ---- out = feat @ wo + bo via MMA (warps 0-7, n-tile = w) ----
        if (lowhalf){
            float d[4] = {0.f,0.f,0.f,0.f};
#pragma unroll 4
            for (int K=0;K<16;K++){
                u32 a0 = __float_as_uint(sm[F_FEAT + g*132 + K*8+tq]);
                u32 a2 = __float_as_uint(sm[F_FEAT + g*132 + K*8+tq+4]);
                float2 bv = *(float2*)&sm[F_WOF + ((K*8+w)*32+lid)*2];
                mma4(d, a0, 0u, a2, 0u, __float_as_uint(bv.x), __float_as_uint(bv.y));
            }
            int c0 = w*8 + 2*tq;
            float v0 = d[0] + sm[F_BO+c0], v1 = d[1] + sm[F_BO+c0+1];
            float2 vv; vv.x = v0; vv.y = v1;
            *(float2*)&out[((size_t)t*8 + g)*64 + c0] = vv;
            bs0 += v0; bq0 += v0*v0;
            bs1 += v1; bq1 += v1*v1;
        }
        __syncthreads();
    }

    if (lowhalf){
        int c0 = w*8 + 2*tq;
        atomicAdd(&sm[F_BNS+c0  ], bs0);
        atomicAdd(&sm[F_BNS+c0+1], bs1);
        atomicAdd(&sm[F_BNQ+c0  ], bq0);
        atomicAdd(&sm[F_BNQ+c0+1], bq1);
    }
    __syncthreads();
    if (tid < 64){
        atomicAdd(&g_sum2[tid],   sm[F_BNS+tid]);
        atomicAdd(&g_sumsq2[tid], sm[F_BNQ+tid]);
    }
}

__global__ void k_fin(const float* __restrict__ g2, const float* __restrict__ be2){
    int j = threadIdx.x;
    double inv = 1.0/(double)Nn;
    double mu  = (double)g_sum2[j]*inv;
    double var = (double)g_sumsq2[j]*inv - mu*mu;
    double a2  = (double)g2[j] / sqrt(var + 1e-5);
    g_a2[j] = (float)a2;
    g_c2[j] = (float)((double)be2[j] - mu*a2);
}

__global__ void k_norm(float* __restrict__ out){
    __shared__ float a2s[64], c2s[64];
    if (threadIdx.x < 64){ a2s[threadIdx.x]=g_a2[threadIdx.x]; c2s[threadIdx.x]=g_c2[threadIdx.x]; }
    __syncthreads();
    const int nq = Nn*64/4;
    float4* o4 = (float4*)out;
    for (int f = blockIdx.x*blockDim.x + threadIdx.x; f < nq; f += gridDim.x*blockDim.x){
        float4 v = o4[f];
        int j = (f*4) & 63;
        v.x = fmaxf(fmaf(v.x, a2s[j],   c2s[j]),   0.f);
        v.y = fmaxf(fmaf(v.y, a2s[j+1], c2s[j+1]), 0.f);
        v.z = fmaxf(fmaf(v.z, a2s[j+2], c2s[j+2]), 0.f);
        v.w = fmaxf(fmaf(v.w, a2s[j+3], c2s[j+3]), 0.f);
        o4[f] = v;
    }
}

extern "C" void kernel_launch(void* const* d_in, const int* in_sizes, int n_in,
                              void* d_out, int out_size){
    const float* p   = (const float*)d_in[0];
    const float* x   = (const float*)d_in[1];
    const float* w1  = (const float*)d_in[2];
    const float* g1  = (const float*)d_in[4];
    const float* be1 = (const float*)d_in[5];
    const float* w2  = (const float*)d_in[6];
    const float* b2  = (const float*)d_in[7];
    const float* ws  = (const float*)d_in[8];
    const float* wo  = (const float*)d_in[9];
    const float* bo  = (const float*)d_in[10];
    const float* g2  = (const float*)d_in[11];
    const float* be2 = (const float*)d_in[12];
    float* out = (float*)d_out;
    (void)in_sizes; (void)n_in; (void)out_size;

    cudaFuncSetAttribute(k_main, cudaFuncAttributeMaxDynamicSharedMemorySize, SMEM_BYTES);

    k_zero<<<1,64>>>();
    k_stats<<<512,256>>>(p);
    k_fold<<<1,128>>>(w1,g1,be1);
    k_main<<<GRID_MAIN,NT,SMEM_BYTES>>>(p,x,w2,b2,ws,wo,bo,out);
    k_fin<<<1,64>>>(g2,be2);
    k_norm<<<2048,256>>>(out);
}

// round 7
// speedup vs baseline: 3.2000x; 1.0515x over previous
#include <cuda_runtime.h>
typedef unsigned int u32;

#define Nn 65536
#define NK (Nn*16)
#define NTILES (Nn/8)
#define NT 512
#define GRID_MAIN 148

// ---- float offsets in dynamic smem ----
#define F_ACT   0          // 128 x 132 A-tile (h, then px)
#define F_A1H   16896      // 128 x 12 layer1-A hi
#define F_A1L   18432      // 128 x 12 layer1-A lo
#define F_W1FH  19968      // layer1 B frags hi: 8n2 x 32 x 4
#define F_W1FL  20992
#define F_W2F   22016      // w2 frags: 16K x 4n2 x 32 x 4
#define F_WSF   30208      // ws frags: 16K x 8n2 x 32 x 4
#define F_WOF   46592      // wo frags: 16K x 8n x 32 x 2
#define F_FEAT  54784      // 8 x 132
#define F_PSM   55840      // 8 x 48
#define F_B2    56224
#define F_BO    56288
#define F_BNS   56352
#define F_BNQ   56416
#define F_TOTAL 56480
#define SMEM_BYTES (F_TOTAL*4)

__device__ __forceinline__ float to_tf32(float x){
    float r; asm("cvt.rna.tf32.f32 %0, %1;":"=f"(r):"f"(x)); return r;
}
__device__ __forceinline__ void mma4(float* d, u32 a0, u32 a1, u32 a2, u32 a3,
                                     u32 b0, u32 b1){
    asm volatile("mma.sync.aligned.m16n8k8.row.col.f32.tf32.tf32.f32 "
        "{%0,%1,%2,%3}, {%4,%5,%6,%7}, {%8,%9}, {%0,%1,%2,%3};"
        : "+f"(d[0]),"+f"(d[1]),"+f"(d[2]),"+f"(d[3])
        : "r"(a0),"r"(a1),"r"(a2),"r"(a3),"r"(b0),"r"(b1));
}

// ---- scratch globals ----
__device__ float g_M1[10], g_M2[55], g_w1p[1280], g_c1[128];
__device__ float g_sum2[64], g_sumsq2[64], g_a2[64], g_c2[64];

__global__ void k_zero(){
    int t = threadIdx.x;
    if (t < 10) g_M1[t]=0.f;
    if (t < 55) g_M2[t]=0.f;
    if (t < 64){ g_sum2[t]=0.f; g_sumsq2[t]=0.f; }
}

// ---- K1: concat moments, center-factored (14 accumulators in k-loop) ----
__global__ void k_stats(const float* __restrict__ p){
    __shared__ float red[8][65];
    float m1[10], m2[55];
#pragma unroll
    for (int i=0;i<10;i++) m1[i]=0.f;
#pragma unroll
    for (int i=0;i<55;i++) m2[i]=0.f;

    int n = blockIdx.x*blockDim.x + threadIdx.x;   // one point per thread
    {
        float4 pr[12];
        const float4* pp = (const float4*)(p + (size_t)n*48);
#pragma unroll
        for (int i=0;i<12;i++) pr[i] = pp[i];
        const float* pc = (const float*)pr;
        float C0=pc[0], C1=pc[1], C2=pc[2];
        float Sq0=0.f,Sq1=0.f,Sq2=0.f;
        float Q00=0.f,Q01=0.f,Q02=0.f,Q11=0.f,Q12=0.f,Q22=0.f;
        float Sd=0.f, Sdq0=0.f,Sdq1=0.f,Sdq2=0.f, Sdd=0.f;
#pragma unroll
        for (int k=0;k<16;k++){
            float qx=pc[3*k], qy=pc[3*k+1], qz=pc[3*k+2];
            float dx=C0-qx, dy=C1-qy, dz=C2-qz;
            float d2 = dx*dx + dy*dy + dz*dz;
            float ds = sqrtf(d2);
            Sq0+=qx; Sq1+=qy; Sq2+=qz;
            Q00=fmaf(qx,qx,Q00); Q01=fmaf(qx,qy,Q01); Q02=fmaf(qx,qz,Q02);
            Q11=fmaf(qy,qy,Q11); Q12=fmaf(qy,qz,Q12); Q22=fmaf(qz,qz,Q22);
            Sd+=ds; Sdq0=fmaf(ds,qx,Sdq0); Sdq1=fmaf(ds,qy,Sdq1); Sdq2=fmaf(ds,qz,Sdq2);
            Sdd+=d2;
        }
        float C[3]={C0,C1,C2};
        float Sq[3]={Sq0,Sq1,Sq2};
        float QQ[3][3]={{Q00,Q01,Q02},{Q01,Q11,Q12},{Q02,Q12,Q22}};
        float SDQ[3]={Sdq0,Sdq1,Sdq2};
        // m1
#pragma unroll
        for (int i=0;i<3;i++){
            m1[i]   += 16.f*C[i];
            m1[3+i] += Sq[i];
            m1[6+i] += 16.f*C[i]-Sq[i];
        }
        m1[9] += Sd;
        // m2, original t-ordering: a=0..9, b=a..9
        int t = 0;
#pragma unroll
        for (int a=0;a<3;a++){
#pragma unroll
            for (int b=a;b<3;b++) m2[t++] += 16.f*C[a]*C[b];        // c,c
#pragma unroll
            for (int b=0;b<3;b++) m2[t++] += C[a]*Sq[b];            // c,q
#pragma unroll
            for (int b=0;b<3;b++) m2[t++] += C[a]*(16.f*C[b]-Sq[b]);// c,d
            m2[t++] += C[a]*Sd;                                     // c,dist
        }
#pragma unroll
        for (int a=0;a<3;a++){
#pragma unroll
            for (int b=a;b<3;b++) m2[t++] += QQ[a][b];              // q,q
#pragma unroll
            for (int b=0;b<3;b++) m2[t++] += C[b]*Sq[a]-QQ[a][b];   // q,d
            m2[t++] += SDQ[a];                                      // q,dist
        }
#pragma unroll
        for (int a=0;a<3;a++){
#pragma unroll
            for (int b=a;b<3;b++)
                m2[t++] += 16.f*C[a]*C[b]-C[a]*Sq[b]-C[b]*Sq[a]+QQ[a][b]; // d,d
            m2[t++] += C[a]*Sd - SDQ[a];                            // d,dist
        }
        m2[t++] += Sdd;                                             // dist^2
    }
#pragma unroll
    for (int off=16; off>0; off>>=1){
#pragma unroll
        for (int i=0;i<10;i++) m1[i] += __shfl_down_sync(0xffffffffu, m1[i], off);
#pragma unroll
        for (int i=0;i<55;i++) m2[i] += __shfl_down_sync(0xffffffffu, m2[i], off);
    }
    int wid = threadIdx.x>>5;
    if ((threadIdx.x&31)==0){
#pragma unroll
        for (int i=0;i<10;i++) red[wid][i]=m1[i];
#pragma unroll
        for (int i=0;i<55;i++) red[wid][10+i]=m2[i];
    }
    __syncthreads();
    if (threadIdx.x < 65){
        float a=0.f;
#pragma unroll
        for (int w=0;w<8;w++) a += red[w][threadIdx.x];
        if (threadIdx.x < 10) atomicAdd(&g_M1[threadIdx.x], a);
        else atomicAdd(&g_M2[threadIdx.x-10], a);
    }
}

__global__ void k_fold(const float* __restrict__ w1, const float* __restrict__ g1,
                       const float* __restrict__ be1){
    int d = threadIdx.x;
    const double invNK = 1.0/(double)NK;
    double wv[10];
#pragma unroll
    for (int c=0;c<10;c++) wv[c] = (double)w1[c*128+d];
    double m = 0.0;
#pragma unroll
    for (int c=0;c<10;c++) m += ((double)g_M1[c]*invNK)*wv[c];
    double q = 0.0; int t = 0;
#pragma unroll
    for (int a=0;a<10;a++)
#pragma unroll
        for (int b=a;b<10;b++){
            double s2 = (double)g_M2[t++]*invNK;
            double term = s2*wv[a]*wv[b];
            q += (a==b) ? term : 2.0*term;
        }
    double var = q - m*m;
    double a1 = (double)g1[d] / sqrt(var + 1e-5);
    g_c1[d] = (float)((double)be1[d] - m*a1);
#pragma unroll
    for (int c=0;c<10;c++) g_w1p[c*128+d] = (float)(wv[c]*a1);
}

// W8 row r (0..7), col c: layer-1 folded weights in A1 basis
__device__ __forceinline__ float w8row(int r, int c){
    switch(r){
        case 0: return g_w1p[384+c] - g_w1p[768+c];
        case 1: return g_w1p[512+c] - g_w1p[896+c];
        case 2: return g_w1p[640+c] - g_w1p[1024+c];
        case 3: return g_w1p[1152+c];
        case 4: return g_w1p[c]     + g_w1p[768+c];
        case 5: return g_w1p[128+c] + g_w1p[896+c];
        case 6: return g_w1p[256+c] + g_w1p[1024+c];
        default: return g_c1[c];
    }
}

__global__ void __launch_bounds__(NT,1) k_main(
    const float* __restrict__ p, const float* __restrict__ x,
    const float* __restrict__ w2, const float* __restrict__ b2,
    const float* __restrict__ ws, const float* __restrict__ wo,
    const float* __restrict__ bo, float* __restrict__ out)
{
    extern __shared__ float sm[];
    int tid = threadIdx.x, w = tid>>5, lid = tid&31;
    int g = lid>>2, tq = lid&3;
    int wl = w & 7;                 // point index for G1/G2/px-stage
    int rA = wl*16;
    bool lowhalf = (w < 8);
    int rg = w & 3, cg = w >> 2;    // G3 roles: rows rg*32..+31, cols 32cg..+31
    int row0 = rg*32;

    // ---- stage weight fragments ----
    for (int i = tid; i < 2048; i += NT){        // w2: [K][n2(4)][lid] float4
        int l2 = i&31, n2 = (i>>5)&3, K = i>>7;
        int g2 = l2>>2, t2 = l2&3;
        int r0 = K*8+t2, r1 = r0+4, c0 = n2*16+g2;
        float4 v;
        v.x = to_tf32(w2[r0*64+c0]);   v.y = to_tf32(w2[r1*64+c0]);
        v.z = to_tf32(w2[r0*64+c0+8]); v.w = to_tf32(w2[r1*64+c0+8]);
        *(float4*)&sm[F_W2F + i*4] = v;
    }
    for (int i = tid; i < 4096; i += NT){        // ws: [K][n2(8)][lid] float4
        int l2 = i&31, n2 = (i>>5)&7, K = i>>8;
        int g2 = l2>>2, t2 = l2&3;
        int r0 = K*8+t2, r1 = r0+4, c0 = n2*16+g2;
        float4 v;
        v.x = to_tf32(ws[r0*128+c0]);   v.y = to_tf32(ws[r1*128+c0]);
        v.z = to_tf32(ws[r0*128+c0+8]); v.w = to_tf32(ws[r1*128+c0+8]);
        *(float4*)&sm[F_WSF + i*4] = v;
    }
    for (int i = tid; i < 4096; i += NT){        // wo: [K][n(8)][lid] float2
        int l2 = i&31, n = (i>>5)&7, K = i>>8;
        int g2 = l2>>2, t2 = l2&3;
        float2 v;
        v.x = to_tf32(wo[(K*8+t2  )*64 + n*8+g2]);
        v.y = to_tf32(wo[(K*8+t2+4)*64 + n*8+g2]);
        *(float2*)&sm[F_WOF + i*2] = v;
    }
    if (tid < 256){                              // layer1 B frags, hi/lo split
        int i = tid, l2 = i&31, n2 = (i>>5)&7;
        int g2 = l2>>2, t2 = l2&3;
#pragma unroll
        for (int j=0;j<2;j++){
            int c = (2*n2+j)*8 + g2;
            float v0 = w8row(t2,   c);
            float v1 = w8row(t2+4, c);
            float h0 = to_tf32(v0), h1 = to_tf32(v1);
            sm[F_W1FH + (n2*32+l2)*4 + 2*j  ] = h0;
            sm[F_W1FH + (n2*32+l2)*4 + 2*j+1] = h1;
            sm[F_W1FL + (n2*32+l2)*4 + 2*j  ] = to_tf32(v0-h0);
            sm[F_W1FL + (n2*32+l2)*4 + 2*j+1] = to_tf32(v1-h1);
        }
    }
    if (tid < 64){ sm[F_B2+tid]=b2[tid]; sm[F_BO+tid]=bo[tid]; sm[F_BNS+tid]=0.f; sm[F_BNQ+tid]=0.f; }
    __syncthreads();

    float bs0=0.f, bs1=0.f, bq0=0.f, bq1=0.f;
    int xrow = wl*16 + (lid>>1);
    int xcol = (lowhalf?0:32) + (lid&1)*16;

    for (int t = blockIdx.x; t < NTILES; t += gridDim.x){
        // prefetch x (16 floats / thread)
        const float4* xp = (const float4*)(x + ((size_t)t*128 + xrow)*64 + xcol);
        float4 xr[4];
#pragma unroll
        for (int i=0;i<4;i++) xr[i] = xp[i];

        if (tid < 96) *(float4*)&sm[F_PSM + tid*4] = *(const float4*)(p + (size_t)t*384 + tid*4);
        __syncthreads();

        // build layer1 A (hi/lo) : row = (pt,k), cols [qx,qy,qz,dist,cx,cy,cz,1]
        if (tid < 128){
            int pt = tid>>4, k = tid&15;
            float cx=sm[F_PSM+pt*48],     cy=sm[F_PSM+pt*48+1],     cz=sm[F_PSM+pt*48+2];
            float qx=sm[F_PSM+pt*48+3*k], qy=sm[F_PSM+pt*48+3*k+1], qz=sm[F_PSM+pt*48+3*k+2];
            float dx=cx-qx, dy=cy-qy, dz=cz-qz;
            float ds = sqrtf(dx*dx+dy*dy+dz*dz);
            float vv[8] = {qx,qy,qz,ds,cx,cy,cz,1.f};
#pragma unroll
            for (int c=0;c<8;c++){
                float hi = to_tf32(vv[c]);
                sm[F_A1H + tid*12 + c] = hi;
                sm[F_A1L + tid*12 + c] = to_tf32(vv[c]-hi);
            }
        }
        __syncthreads();

        // ---- GEMM1 (K=8, split tf32): h = relu(A1 @ W8) -> ACT ----
        {
            u32 ah0 = __float_as_uint(sm[F_A1H + (rA+g  )*12 + tq]);
            u32 ah1 = __float_as_uint(sm[F_A1H + (rA+g+8)*12 + tq]);
            u32 ah2 = __float_as_uint(sm[F_A1H + (rA+g  )*12 + tq+4]);
            u32 ah3 = __float_as_uint(sm[F_A1H + (rA+g+8)*12 + tq+4]);
            u32 al0 = __float_as_uint(sm[F_A1L + (rA+g  )*12 + tq]);
            u32 al1 = __float_as_uint(sm[F_A1L + (rA+g+8)*12 + tq]);
            u32 al2 = __float_as_uint(sm[F_A1L + (rA+g  )*12 + tq+4]);
            u32 al3 = __float_as_uint(sm[F_A1L + (rA+g+8)*12 + tq+4]);
            int n2b = lowhalf ? 0 : 4;
#pragma unroll
            for (int j=0;j<4;j++){
                int n2g = n2b + j;
                float4 bh = *(float4*)&sm[F_W1FH + (n2g*32+lid)*4];
                float4 bl = *(float4*)&sm[F_W1FL + (n2g*32+lid)*4];
#pragma unroll
                for (int par=0;par<2;par++){
                    float d[4] = {0.f,0.f,0.f,0.f};
                    u32 b0 = __float_as_uint(par? bh.z : bh.x);
                    u32 b1 = __float_as_uint(par? bh.w : bh.y);
                    u32 c0u= __float_as_uint(par? bl.z : bl.x);
                    u32 c1u= __float_as_uint(par? bl.w : bl.y);
                    mma4(d, ah0,ah1,ah2,ah3, b0,b1);
                    mma4(d, al0,al1,al2,al3, b0,b1);
                    mma4(d, ah0,ah1,ah2,ah3, c0u,c1u);
                    int c0 = (n2g*2+par)*8 + 2*tq;
                    float2 lo, hi;
                    lo.x = to_tf32(fmaxf(d[0],0.f)); lo.y = to_tf32(fmaxf(d[1],0.f));
                    hi.x = to_tf32(fmaxf(d[2],0.f)); hi.y = to_tf32(fmaxf(d[3],0.f));
                    *(float2*)&sm[F_ACT + (rA+g  )*132 + c0] = lo;
                    *(float2*)&sm[F_ACT + (rA+g+8)*132 + c0] = hi;
                }
            }
        }
        __syncthreads();

        // ---- GEMM2: p_c = h @ w2 (mt=1 point wl, 4 n-tiles per warp) ----
        float d2[4][4];
#pragma unroll
        for (int n=0;n<4;n++){ d2[n][0]=0.f; d2[n][1]=0.f; d2[n][2]=0.f; d2[n][3]=0.f; }
        {
            int n2b = lowhalf ? 0 : 2;
#pragma unroll 4
            for (int K=0;K<16;K++){
                const float* ar = &sm[F_ACT + K*8 + tq];
                u32 a0 = __float_as_uint(ar[(rA+g  )*132]);
                u32 a1 = __float_as_uint(ar[(rA+g+8)*132]);
                u32 a2 = __float_as_uint(ar[(rA+g  )*132+4]);
                u32 a3 = __float_as_uint(ar[(rA+g+8)*132+4]);
                float4 b0 = *(float4*)&sm[F_W2F + ((K*4+n2b  )*32+lid)*4];
                float4 b1 = *(float4*)&sm[F_W2F + ((K*4+n2b+1)*32+lid)*4];
                mma4(d2[0], a0,a1,a2,a3, __float_as_uint(b0.x), __float_as_uint(b0.y));
                mma4(d2[1], a0,a1,a2,a3, __float_as_uint(b0.z), __float_as_uint(b0.w));
                mma4(d2[2], a0,a1,a2,a3, __float_as_uint(b1.x), __float_as_uint(b1.y));
                mma4(d2[3], a0,a1,a2,a3, __float_as_uint(b1.z), __float_as_uint(b1.w));
            }
        }
        // write px = [p_c + b2 | x]
        {
            int nb = lowhalf ? 0 : 4;
#pragma unroll
            for (int n=0;n<4;n++){
                int c0 = (nb+n)*8 + 2*tq;
                float ba = sm[F_B2+c0], bb = sm[F_B2+c0+1];
                float2 lo, hi;
                lo.x = to_tf32(d2[n][0]+ba); lo.y = to_tf32(d2[n][1]+bb);
                hi.x = to_tf32(d2[n][2]+ba); hi.y = to_tf32(d2[n][3]+bb);
                *(float2*)&sm[F_ACT + (rA+g  )*132 + c0] = lo;
                *(float2*)&sm[F_ACT + (rA+g+8)*132 + c0] = hi;
            }
#pragma unroll
            for (int i=0;i<4;i++){
                float4 v = xr[i], wv;
                wv.x=to_tf32(v.x); wv.y=to_tf32(v.y); wv.z=to_tf32(v.z); wv.w=to_tf32(v.w);
                *(float4*)&sm[F_ACT + xrow*132 + 64 + xcol + i*4] = wv;
            }
        }
        __syncthreads();

        // ---- GEMM3: logits = px @ ws (mt=2: rows rg*32..+31, nt=4: cols 32cg..+31) ----
        float d3[2][4][4];
#pragma unroll
        for (int m=0;m<2;m++)
#pragma unroll
            for (int n=0;n<4;n++){ d3[m][n][0]=0.f; d3[m][n][1]=0.f; d3[m][n][2]=0.f; d3[m][n][3]=0.f; }
        {
#pragma unroll 2
            for (int K=0;K<16;K++){
                const float* ar = &sm[F_ACT + K*8 + tq];
                u32 a[2][4];
#pragma unroll
                for (int m=0;m<2;m++){
                    int rb = row0 + m*16;
                    a[m][0] = __float_as_uint(ar[(rb+g  )*132]);
                    a[m][1] = __float_as_uint(ar[(rb+g+8)*132]);
                    a[m][2] = __float_as_uint(ar[(rb+g  )*132+4]);
                    a[m][3] = __float_as_uint(ar[(rb+g+8)*132+4]);
                }
                float4 b0 = *(float4*)&sm[F_WSF + ((K*8 + 2*cg  )*32+lid)*4];
                float4 b1 = *(float4*)&sm[F_WSF + ((K*8 + 2*cg+1)*32+lid)*4];
#pragma unroll
                for (int m=0;m<2;m++){
                    mma4(d3[m][0], a[m][0],a[m][1],a[m][2],a[m][3], __float_as_uint(b0.x), __float_as_uint(b0.y));
                    mma4(d3[m][1], a[m][0],a[m][1],a[m][2],a[m][3], __float_as_uint(b0.z), __float_as_uint(b0.w));
                    mma4(d3[m][2], a[m][0],a[m][1],a[m][2],a[m][3], __float_as_uint(b1.x), __float_as_uint(b1.y));
                    mma4(d3[m][3], a[m][0],a[m][1],a[m][2],a[m][3], __float_as_uint(b1.z), __float_as_uint(b1.w));
                }
            }
        }

        // ---- softmax over k + pooled feat (2 points x 4 n-tiles per warp) ----
#pragma unroll
        for (int m=0;m<2;m++){
            int pt = 2*rg + m;
            int rb = row0 + m*16;
#pragma unroll
            for (int nl=0; nl<4; nl++){
                int c0 = (4*cg+nl)*8 + 2*tq;
                float e0 = __expf(d3[m][nl][0]), e1 = __expf(d3[m][nl][1]);
                float e2 = __expf(d3[m][nl][2]), e3 = __expf(d3[m][nl][3]);
                float2 plo = *(float2*)&sm[F_ACT + (rb+g  )*132 + c0];
                float2 phi = *(float2*)&sm[F_ACT + (rb+g+8)*132 + c0];
                float se = e0+e2, so = e1+e3;
                float ve = fmaf(e0, plo.x, e2*phi.x);
                float vo = fmaf(e1, plo.y, e3*phi.y);
#pragma unroll
                for (int mm=4;mm<32;mm<<=1){
                    se += __shfl_xor_sync(0xffffffffu, se, mm);
                    so += __shfl_xor_sync(0xffffffffu, so, mm);
                    ve += __shfl_xor_sync(0xffffffffu, ve, mm);
                    vo += __shfl_xor_sync(0xffffffffu, vo, mm);
                }
                if (lid < 4){
                    float2 f; f.x = ve/se; f.y = vo/so;
                    *(float2*)&sm[F_FEAT + pt*132 + c0] = f;
                }
            }
        }
        __syncthreads();

        // ---- out = feat @ wo + bo via MMA (warps 0-7, n-tile = w) ----
        if (lowhalf){
            float d[4] = {0.f,0.f,0.f,0.f};
#pragma unroll 4
            for (int K=0;K<16;K++){
                u32 a0 = __float_as_uint(sm[F_FEAT + g*132 + K*8+tq]);
                u32 a2 = __float_as_uint(sm[F_FEAT + g*132 + K*8+tq+4]);
                float2 bv = *(float2*)&sm[F_WOF + ((K*8+w)*32+lid)*2];
                mma4(d, a0, 0u, a2, 0u, __float_as_uint(bv.x), __float_as_uint(bv.y));
            }
            int c0 = w*8 + 2*tq;
            float v0 = d[0] + sm[F_BO+c0], v1 = d[1] + sm[F_BO+c0+1];
            float2 vv; vv.x = v0; vv.y = v1;
            *(float2*)&out[((size_t)t*8 + g)*64 + c0] = vv;
            bs0 += v0; bq0 += v0*v0;
            bs1 += v1; bq1 += v1*v1;
        }
        __syncthreads();
    }

    if (lowhalf){
        int c0 = w*8 + 2*tq;
        atomicAdd(&sm[F_BNS+c0  ], bs0);
        atomicAdd(&sm[F_BNS+c0+1], bs1);
        atomicAdd(&sm[F_BNQ+c0  ], bq0);
        atomicAdd(&sm[F_BNQ+c0+1], bq1);
    }
    __syncthreads();
    if (tid < 64){
        atomicAdd(&g_sum2[tid],   sm[F_BNS+tid]);
        atomicAdd(&g_sumsq2[tid], sm[F_BNQ+tid]);
    }
}

__global__ void k_fin(const float* __restrict__ g2, const float* __restrict__ be2){
    int j = threadIdx.x;
    double inv = 1.0/(double)Nn;
    double mu  = (double)g_sum2[j]*inv;
    double var = (double)g_sumsq2[j]*inv - mu*mu;
    double a2  = (double)g2[j] / sqrt(var + 1e-5);
    g_a2[j] = (float)a2;
    g_c2[j] = (float)((double)be2[j] - mu*a2);
}

__global__ void k_norm(float* __restrict__ out){
    __shared__ float a2s[64], c2s[64];
    if (threadIdx.x < 64){ a2s[threadIdx.x]=g_a2[threadIdx.x]; c2s[threadIdx.x]=g_c2[threadIdx.x]; }
    __syncthreads();
    const int nq = Nn*64/4;
    float4* o4 = (float4*)out;
    for (int f = blockIdx.x*blockDim.x + threadIdx.x; f < nq; f += gridDim.x*blockDim.x){
        float4 v = o4[f];
        int j = (f*4) & 63;
        v.x = fmaxf(fmaf(v.x, a2s[j],   c2s[j]),   0.f);
        v.y = fmaxf(fmaf(v.y, a2s[j+1], c2s[j+1]), 0.f);
        v.z = fmaxf(fmaf(v.z, a2s[j+2], c2s[j+2]), 0.f);
        v.w = fmaxf(fmaf(v.w, a2s[j+3], c2s[j+3]), 0.f);
        o4[f] = v;
    }
}

extern "C" void kernel_launch(void* const* d_in, const int* in_sizes, int n_in,
                              void* d_out, int out_size){
    const float* p   = (const float*)d_in[0];
    const float* x   = (const float*)d_in[1];
    const float* w1  = (const float*)d_in[2];
    const float* g1  = (const float*)d_in[4];
    const float* be1 = (const float*)d_in[5];
    const float* w2  = (const float*)d_in[6];
    const float* b2  = (const float*)d_in[7];
    const float* ws  = (const float*)d_in[8];
    const float* wo  = (const float*)d_in[9];
    const float* bo  = (const float*)d_in[10];
    const float* g2  = (const float*)d_in[11];
    const float* be2 = (const float*)d_in[12];
    float* out = (float*)d_out;
    (void)in_sizes; (void)n_in; (void)out_size;

    cudaFuncSetAttribute(k_main, cudaFuncAttributeMaxDynamicSharedMemorySize, SMEM_BYTES);

    k_zero<<<1,64>>>();
    k_stats<<<256,256>>>(p);
    k_fold<<<1,128>>>(w1,g1,be1);
    k_main<<<GRID_MAIN,NT,SMEM_BYTES>>>(p,x,w2,b2,ws,wo,bo,out);
    k_fin<<<1,64>>>(g2,be2);
    k_norm<<<2048,256>>>(out);
}